// round 1
// baseline (speedup 1.0000x reference)
#include <cuda_runtime.h>
#include <cstdint>
#include <math.h>

#define NPTS    4096
#define MAXQ    65536
#define THREADS 256
#define IPT     4
#define QPB     (THREADS * IPT)       // 1024 queries per block
#define JCHUNK  256                   // candidates per block (== THREADS)
#define NCHUNK  (NPTS / JCHUNK)       // 16

// Scratch: packed (key(e) << 32 | local_idx) per query, per direction.
__device__ unsigned long long g_best1[MAXQ];
__device__ unsigned long long g_best2[MAXQ];

// Order-preserving float -> uint32 mapping (total order, works for negatives).
__device__ __forceinline__ unsigned int fkey(float f) {
    unsigned int b = __float_as_uint(f);
    return (b & 0x80000000u) ? ~b : (b | 0x80000000u);
}
__device__ __forceinline__ float fdekey(unsigned int k) {
    unsigned int b = (k & 0x80000000u) ? (k & 0x7FFFFFFFu) : ~k;
    return __uint_as_float(b);
}

__global__ void __launch_bounds__(THREADS) init_kernel(float* out, int nq) {
    int i = blockIdx.x * blockDim.x + threadIdx.x;
    if (i < nq) {
        g_best1[i] = ~0ull;
        g_best2[i] = ~0ull;
    }
    if (i == 0) out[0] = 0.0f;
}

// Brute-force NN: for each query in Q, min over a JCHUNK slice of C (same batch)
// of e = |c|^2 - 2 <q, c>.  argmin(e) == argmin(d) since d = |q|^2 + e.
__global__ void __launch_bounds__(THREADS) nn_kernel(
    const float* __restrict__ Q,   // queries,   [B, NPTS, 6]
    const float* __restrict__ C,   // candidates,[B, NPTS, 6]
    int dir)                       // 0 -> g_best1, 1 -> g_best2
{
    __shared__ float4 tile[JCHUNK];

    unsigned long long* best = dir ? g_best2 : g_best1;

    const int tid    = threadIdx.x;
    const int chunk  = blockIdx.x;          // 0..NCHUNK-1
    const int qblock = blockIdx.y;
    const int qbase  = qblock * QPB;
    const int batch  = qbase / NPTS;        // QPB divides NPTS
    const int jbase  = batch * NPTS + chunk * JCHUNK;

    // Stage candidate slice: {x, y, z, |p|^2}
    {
        const float* p = C + (size_t)(jbase + tid) * 6;
        float x = p[0], y = p[1], z = p[2];
        tile[tid] = make_float4(x, y, z, fmaf(x, x, fmaf(y, y, z * z)));
    }
    __syncthreads();

    float x1[IPT], y1[IPT], z1[IPT], be[IPT];
    int   bj[IPT], qi[IPT];
#pragma unroll
    for (int i = 0; i < IPT; i++) {
        qi[i] = qbase + i * THREADS + tid;
        const float* p = Q + (size_t)qi[i] * 6;
        x1[i] = p[0]; y1[i] = p[1]; z1[i] = p[2];
        be[i] = 3.4e38f;
        bj[i] = 0;
    }

#pragma unroll 4
    for (int jj = 0; jj < JCHUNK; jj++) {
        float4 c = tile[jj];
#pragma unroll
        for (int i = 0; i < IPT; i++) {
            float t = fmaf(z1[i], c.z, fmaf(y1[i], c.y, x1[i] * c.x));
            float e = fmaf(-2.0f, t, c.w);
            if (e < be[i]) { be[i] = e; bj[i] = jj; }   // strict '<' keeps first min
        }
    }

#pragma unroll
    for (int i = 0; i < IPT; i++) {
        // local index within batch in low bits -> ties resolve to smallest idx,
        // matching jnp.argmin's first-occurrence semantics.
        unsigned int lidx = (unsigned int)(chunk * JCHUNK + bj[i]);
        unsigned long long key =
            ((unsigned long long)fkey(be[i]) << 32) | lidx;
        atomicMin(&best[qi[i]], key);
    }
}

__device__ __forceinline__ float normal_diff2(const float* __restrict__ a,
                                              const float* __restrict__ b) {
    float ax = a[0], ay = a[1], az = a[2];
    float bx = b[0], by = b[1], bz = b[2];
    float ia = 1.0f / fmaxf(sqrtf(fmaf(ax, ax, fmaf(ay, ay, az * az))), 1e-12f);
    float ib = 1.0f / fmaxf(sqrtf(fmaf(bx, bx, fmaf(by, by, bz * bz))), 1e-12f);
    float dx = ax * ia - bx * ib;
    float dy = ay * ia - by * ib;
    float dz = az * ia - bz * ib;
    return fmaf(dx, dx, fmaf(dy, dy, dz * dz));
}

// Decode best keys, gather neighbor normals, compute dist + normal terms,
// reduce to scalar. All four means share the same denominator (B*NPTS).
__global__ void __launch_bounds__(THREADS) reduce_kernel(
    const float* __restrict__ X1, const float* __restrict__ X2,
    float* __restrict__ out, int nq, float inv_nq)
{
    int q = blockIdx.x * blockDim.x + threadIdx.x;
    float c = 0.0f;
    if (q < nq) {
        int batch = q / NPTS;
        {   // direction 1: query X1, neighbor in X2
            unsigned long long k = g_best1[q];
            int   idx = (int)(unsigned int)(k & 0xFFFFFFFFull);
            float e   = fdekey((unsigned int)(k >> 32));
            const float* p = X1 + (size_t)q * 6;
            float s1 = fmaf(p[0], p[0], fmaf(p[1], p[1], p[2] * p[2]));
            const float* n2 = X2 + (size_t)(batch * NPTS + idx) * 6 + 3;
            c += (s1 + e) + normal_diff2(p + 3, n2);
        }
        {   // direction 2: query X2, neighbor in X1
            unsigned long long k = g_best2[q];
            int   idx = (int)(unsigned int)(k & 0xFFFFFFFFull);
            float e   = fdekey((unsigned int)(k >> 32));
            const float* p = X2 + (size_t)q * 6;
            float s2 = fmaf(p[0], p[0], fmaf(p[1], p[1], p[2] * p[2]));
            const float* n1 = X1 + (size_t)(batch * NPTS + idx) * 6 + 3;
            c += (s2 + e) + normal_diff2(p + 3, n1);
        }
    }

    // Block reduction
    __shared__ float ssum[THREADS / 32];
    float v = c;
#pragma unroll
    for (int o = 16; o > 0; o >>= 1)
        v += __shfl_down_sync(0xFFFFFFFFu, v, o);
    int lane = threadIdx.x & 31;
    int warp = threadIdx.x >> 5;
    if (lane == 0) ssum[warp] = v;
    __syncthreads();
    if (warp == 0) {
        v = (lane < THREADS / 32) ? ssum[lane] : 0.0f;
#pragma unroll
        for (int o = 4; o > 0; o >>= 1)
            v += __shfl_down_sync(0xFFFFFFFFu, v, o);
        if (lane == 0) atomicAdd(out, v * inv_nq);
    }
}

extern "C" void kernel_launch(void* const* d_in, const int* in_sizes, int n_in,
                              void* d_out, int out_size)
{
    const float* x1 = (const float*)d_in[0];
    const float* x2 = (const float*)d_in[1];
    float* out = (float*)d_out;

    int total = in_sizes[0];
    int B  = total / (NPTS * 6);     // expected 8
    int nq = B * NPTS;               // 32768

    init_kernel<<<(nq + THREADS - 1) / THREADS, THREADS>>>(out, nq);

    dim3 grid(NCHUNK, nq / QPB);     // (16, 32) -> 512 CTAs per direction
    nn_kernel<<<grid, THREADS>>>(x1, x2, 0);   // dist1 / idx1
    nn_kernel<<<grid, THREADS>>>(x2, x1, 1);   // dist2 / idx2

    reduce_kernel<<<(nq + THREADS - 1) / THREADS, THREADS>>>(
        x1, x2, out, nq, 1.0f / (float)nq);
}

// round 2
// speedup vs baseline: 1.1511x; 1.1511x over previous
#include <cuda_runtime.h>
#include <cstdint>
#include <math.h>

#define NPTS    4096
#define MAXQ    32768          // B=8 * 4096
#define THREADS 256
#define QPAIRS  4              // query pairs per thread (8 queries)
#define QPT     (QPAIRS * 2)
#define QPB     (THREADS * QPT)   // 2048 queries per block
#define JCHUNK  256               // candidates per block
#define NCHUNK  (NPTS / JCHUNK)   // 16
#define NGROUP  64                // index-quantization group
#define NRED    256               // reduce blocks

typedef unsigned long long ull;

// Partial results: (quantized d_bits << 32) | idx-within-batch, per (dir, chunk, query)
__device__ ull   g_part[2][NCHUNK][MAXQ];
__device__ float g_bsum[NRED];

__device__ __forceinline__ ull fma2(ull a, ull b, ull c) {
    ull d;
    asm("fma.rn.f32x2 %0, %1, %2, %3;" : "=l"(d) : "l"(a), "l"(b), "l"(c));
    return d;
}
__device__ __forceinline__ ull add2(ull a, ull b) {
    ull d;
    asm("add.rn.f32x2 %0, %1, %2;" : "=l"(d) : "l"(a), "l"(b));
    return d;
}
__device__ __forceinline__ ull pack2(float lo, float hi) {
    ull d;
    asm("mov.b64 %0, {%1, %2};" : "=l"(d) : "f"(lo), "f"(hi));
    return d;
}
__device__ __forceinline__ ull dup2(float v) { return pack2(v, v); }
__device__ __forceinline__ unsigned int lo32(ull v) { return (unsigned int)v; }
__device__ __forceinline__ unsigned int hi32(ull v) { return (unsigned int)(v >> 32); }

// NN kernel: queries packed 2-per-f32x2-lane, candidates broadcast from a
// duplicated smem tile. Tracks min of key = (d_bits & ~63) | local_idx via
// unsigned IMNMX (d >= 0 so float bits are uint-ordered).
__global__ void __launch_bounds__(THREADS) nn_kernel(
    const float* __restrict__ X1, const float* __restrict__ X2)
{
    __shared__ ull tile[JCHUNK][4];   // per candidate: {xx, yy, zz, ww(|c|^2)}

    const int dir    = blockIdx.z;            // 0: Q=X1,C=X2   1: Q=X2,C=X1
    const float* __restrict__ Q = dir ? X2 : X1;
    const float* __restrict__ C = dir ? X1 : X2;

    const int tid    = threadIdx.x;
    const int chunk  = blockIdx.x;             // 0..NCHUNK-1
    const int qbase  = blockIdx.y * QPB;
    const int batch  = qbase / NPTS;           // QPB divides NPTS
    const int jloc   = chunk * JCHUNK;         // candidate base within batch

    // Stage candidate slice, coordinates duplicated for broadcast packing.
    {
        const float* p = C + (size_t)(batch * NPTS + jloc + tid) * 6;
        float x = p[0], y = p[1], z = p[2];
        tile[tid][0] = dup2(x);
        tile[tid][1] = dup2(y);
        tile[tid][2] = dup2(z);
        tile[tid][3] = dup2(fmaf(x, x, fmaf(y, y, z * z)));
    }
    __syncthreads();

    // Load queries: fold -2 into coords; s = |q|^2 so tracked value is d >= 0.
    ull nx[QPAIRS], ny[QPAIRS], nz[QPAIRS], sq[QPAIRS];
    int q0[QPAIRS];
#pragma unroll
    for (int p = 0; p < QPAIRS; p++) {
        q0[p] = qbase + (p * THREADS + tid) * 2;
        const float* a = Q + (size_t)q0[p] * 6;
        const float* b = a + 6;
        nx[p] = pack2(-2.0f * a[0], -2.0f * b[0]);
        ny[p] = pack2(-2.0f * a[1], -2.0f * b[1]);
        nz[p] = pack2(-2.0f * a[2], -2.0f * b[2]);
        sq[p] = pack2(fmaf(a[0], a[0], fmaf(a[1], a[1], a[2] * a[2])),
                      fmaf(b[0], b[0], fmaf(b[1], b[1], b[2] * b[2])));
    }

    unsigned int bestk[QPT], bestg[QPT];
#pragma unroll
    for (int q = 0; q < QPT; q++) { bestk[q] = 0xFFFFFFFFu; bestg[q] = 0; }

    const ull* tp = &tile[0][0];
    for (int g = 0; g < JCHUNK / NGROUP; g++) {
        unsigned int k[QPT];
#pragma unroll
        for (int q = 0; q < QPT; q++) k[q] = 0xFFFFFFFFu;

        unsigned int u = 0;
#pragma unroll 8
        for (int cc = 0; cc < NGROUP; cc++) {
            ull cxx = tp[0], cyy = tp[1], czz = tp[2], cww = tp[3];
            tp += 4;
#pragma unroll
            for (int p = 0; p < QPAIRS; p++) {
                ull t = fma2(nz[p], czz, cww);
                t = fma2(ny[p], cyy, t);
                t = fma2(nx[p], cxx, t);
                t = add2(t, sq[p]);            // d = |q - c|^2 (two queries)
                unsigned int k0 = (lo32(t) & 0xFFFFFFC0u) | u;   // LOP3
                unsigned int k1 = (hi32(t) & 0xFFFFFFC0u) | u;   // LOP3
                k[2 * p]     = min(k[2 * p],     k0);             // IMNMX.U32
                k[2 * p + 1] = min(k[2 * p + 1], k1);
            }
            u++;
        }
#pragma unroll
        for (int q = 0; q < QPT; q++)
            if (k[q] < bestk[q]) { bestk[q] = k[q]; bestg[q] = (unsigned int)g; }
    }

#pragma unroll
    for (int p = 0; p < QPAIRS; p++) {
#pragma unroll
        for (int h = 0; h < 2; h++) {
            int q = q0[p] + h;
            unsigned int bk = bestk[2 * p + h];
            unsigned int idx = (unsigned int)jloc + bestg[2 * p + h] * NGROUP + (bk & 63u);
            g_part[dir][chunk][q] = ((ull)(bk & 0xFFFFFFC0u) << 32) | idx;
        }
    }
}

__device__ __forceinline__ float normal_diff2(const float* __restrict__ a,
                                              const float* __restrict__ b) {
    float ax = a[0], ay = a[1], az = a[2];
    float bx = b[0], by = b[1], bz = b[2];
    float ia = 1.0f / fmaxf(sqrtf(fmaf(ax, ax, fmaf(ay, ay, az * az))), 1e-12f);
    float ib = 1.0f / fmaxf(sqrtf(fmaf(bx, bx, fmaf(by, by, bz * bz))), 1e-12f);
    float dx = ax * ia - bx * ib;
    float dy = ay * ia - by * ib;
    float dz = az * ia - bz * ib;
    return fmaf(dx, dx, fmaf(dy, dy, dz * dz));
}

// Merge the NCHUNK partials per (dir, query), gather normals, partial-sum per block.
__global__ void __launch_bounds__(THREADS) reduce_kernel(
    const float* __restrict__ X1, const float* __restrict__ X2, int nq)
{
    int gi = blockIdx.x * blockDim.x + threadIdx.x;   // 0 .. 2*nq-1
    float c = 0.0f;
    if (gi < 2 * nq) {
        int dir = gi >= nq;
        int q   = dir ? gi - nq : gi;
        int batch = q / NPTS;

        ull best = ~0ull;
#pragma unroll
        for (int ch = 0; ch < NCHUNK; ch++) {
            ull v = g_part[dir][ch][q];
            best = (v < best) ? v : best;
        }
        float d  = __uint_as_float((unsigned int)(best >> 32));
        int  idx = (int)(best & 0xFFFFFFFFull);

        const float* Qn = (dir ? X2 : X1) + (size_t)q * 6 + 3;
        const float* Cn = (dir ? X1 : X2) + (size_t)(batch * NPTS + idx) * 6 + 3;
        c = d + normal_diff2(Qn, Cn);
    }

    __shared__ float ssum[THREADS / 32];
    float v = c;
#pragma unroll
    for (int o = 16; o > 0; o >>= 1) v += __shfl_down_sync(0xFFFFFFFFu, v, o);
    int lane = threadIdx.x & 31, warp = threadIdx.x >> 5;
    if (lane == 0) ssum[warp] = v;
    __syncthreads();
    if (warp == 0) {
        v = (lane < THREADS / 32) ? ssum[lane] : 0.0f;
#pragma unroll
        for (int o = 4; o > 0; o >>= 1) v += __shfl_down_sync(0xFFFFFFFFu, v, o);
        if (lane == 0) g_bsum[blockIdx.x] = v;
    }
}

__global__ void __launch_bounds__(NRED) final_kernel(float* out, float inv_nq) {
    float v = g_bsum[threadIdx.x];
#pragma unroll
    for (int o = 16; o > 0; o >>= 1) v += __shfl_down_sync(0xFFFFFFFFu, v, o);
    __shared__ float ssum[NRED / 32];
    int lane = threadIdx.x & 31, warp = threadIdx.x >> 5;
    if (lane == 0) ssum[warp] = v;
    __syncthreads();
    if (warp == 0) {
        v = (lane < NRED / 32) ? ssum[lane] : 0.0f;
#pragma unroll
        for (int o = 4; o > 0; o >>= 1) v += __shfl_down_sync(0xFFFFFFFFu, v, o);
        if (lane == 0) out[0] = v * inv_nq;
    }
}

extern "C" void kernel_launch(void* const* d_in, const int* in_sizes, int n_in,
                              void* d_out, int out_size)
{
    const float* x1 = (const float*)d_in[0];
    const float* x2 = (const float*)d_in[1];
    float* out = (float*)d_out;

    int total = in_sizes[0];
    int B  = total / (NPTS * 6);      // 8
    int nq = B * NPTS;                // 32768

    dim3 grid(NCHUNK, nq / QPB, 2);   // (16, 16, 2) = 512 CTAs
    nn_kernel<<<grid, THREADS>>>(x1, x2);

    int rblocks = (2 * nq + THREADS - 1) / THREADS;   // 256
    reduce_kernel<<<rblocks, THREADS>>>(x1, x2, nq);

    final_kernel<<<1, NRED>>>(out, 1.0f / (float)nq);
}